// round 17
// baseline (speedup 1.0000x reference)
#include <cuda_runtime.h>
#include <cuda_fp16.h>
#include <cstdint>

#define H     64
#define F     5
#define BS    32     // samples per CTA; grid = 4096/32 = 128, single wave
#define TPB   256
#define RB    128
#define SLO   (1.f / 2048.f)   // lo-pass scale fixup

// word-indexed SMEM, per parity: BH 1056 | BL 1056 | X1 264 | X2 264
#define BH_W   0
#define BL_W   1056
#define X1_W   2112
#define X2_W   2376
#define PW     2640
#define HFIN_W (2 * PW)          // 64 x 33 floats
#define TOTW   (HFIN_W + 64 * 33)

__device__ float g_rank_part[RB];
__device__ float g_reg_part[2];

__device__ __forceinline__ float tanh_hw(float x) {
    float y; asm("tanh.approx.f32 %0, %1;" : "=f"(y) : "f"(x)); return y;
}
__device__ __forceinline__ float sig_hw(float x) {
    return fmaf(tanh_hw(0.5f * x), 0.5f, 0.5f);
}
__device__ __forceinline__ uint32_t packh2(__half a, __half b) {   // a -> low (even k)
    __half2 h = __halves2half2(a, b);
    return *(uint32_t*)&h;
}
__device__ __forceinline__ void mma16(float* c, const uint32_t* a, const uint32_t* b) {
    asm volatile("mma.sync.aligned.m16n8k16.row.col.f32.f16.f16.f32 "
        "{%0,%1,%2,%3}, {%4,%5,%6,%7}, {%8,%9}, {%0,%1,%2,%3};"
        : "+f"(c[0]), "+f"(c[1]), "+f"(c[2]), "+f"(c[3])
        : "r"(a[0]), "r"(a[1]), "r"(a[2]), "r"(a[3]), "r"(b[0]), "r"(b[1]));
}
// halfword index of B element (k, sample s) within a chunk region starting at baseW
__device__ __forceinline__ int hw_idx(int baseW, int k, int s) {
    int kk = k & 15;
    int r = (kk >> 3) & 1, tqt = (kk >> 1) & 3, i = kk & 1;
    int word = baseW + ((k >> 4) * 4 + (s >> 3)) * 66 + ((s & 7) * 4 + tqt) * 2 + r;
    return word * 2 + i;
}

__global__ __launch_bounds__(TPB, 1)
void lstm_kernel(const float* __restrict__ feature,
                 const float* __restrict__ Wih, const float* __restrict__ Whh,
                 const float* __restrict__ bih, const float* __restrict__ bhh,
                 const float* __restrict__ Wd,  const float* __restrict__ bd,
                 float* __restrict__ pred, int N, int T)
{
    __shared__ uint32_t smw[TOTW];
    __half* hp = (__half*)smw;

    const int tid = threadIdx.x, w = tid >> 5, lane = tid & 31;
    const int g   = lane >> 2,  tq = lane & 3;
    const int u   = 8 * w + g;                 // this thread's hidden unit
    const int n0  = blockIdx.x * BS;

    // ---- A fragments (fp16 hi + scaled-lo), gate-permuted rows ----
    uint32_t aHi[2][4][4], aLo[2][4][4], AE1[2][4], AE2[2][4];
#pragma unroll
    for (int mt = 0; mt < 2; mt++) {
        const int rA = (2 * mt) * H + u, rB = (2 * mt + 1) * H + u;
#pragma unroll
        for (int kc = 0; kc < 4; kc++) {
#pragma unroll
            for (int half8 = 0; half8 < 2; half8++) {
                const int k0 = 16 * kc + 2 * tq + 8 * half8;
#pragma unroll
                for (int rr = 0; rr < 2; rr++) {
                    const int row = rr ? rB : rA;
                    float w0 = Whh[row * H + k0], w1 = Whh[row * H + k0 + 1];
                    __half h0 = __float2half_rn(w0), h1 = __float2half_rn(w1);
                    __half l0 = __float2half_rn((w0 - __half2float(h0)) * 2048.f);
                    __half l1 = __float2half_rn((w1 - __half2float(h1)) * 2048.f);
                    aHi[mt][kc][2 * half8 + rr] = packh2(h0, h1);
                    aLo[mt][kc][2 * half8 + rr] = packh2(l0, l1);
                }
            }
        }
        // ext A: AE1 k0-4 = Wih_hi; AE2 k0-4 = Wih_lo', k5-9 = Wih_hi
        auto ev1 = [&](int row, int k) -> __half {
            if (k < 5) return __float2half_rn(Wih[row * F + k]);
            return __float2half_rn(0.f);
        };
        auto ev2 = [&](int row, int k) -> __half {
            if (k < 5) {
                float wv = Wih[row * F + k];
                __half hh = __float2half_rn(wv);
                return __float2half_rn((wv - __half2float(hh)) * 2048.f);
            }
            if (k < 10) return __float2half_rn(Wih[row * F + (k - 5)]);
            return __float2half_rn(0.f);
        };
#pragma unroll
        for (int half8 = 0; half8 < 2; half8++) {
            const int k0 = 2 * tq + 8 * half8;
#pragma unroll
            for (int rr = 0; rr < 2; rr++) {
                const int row = rr ? rB : rA;
                AE1[mt][2 * half8 + rr] = packh2(ev1(row, k0), ev1(row, k0 + 1));
                AE2[mt][2 * half8 + rr] = packh2(ev2(row, k0), ev2(row, k0 + 1));
            }
        }
    }
    float bi[4];
#pragma unroll
    for (int gg = 0; gg < 4; gg++) bi[gg] = bih[gg * H + u] + bhh[gg * H + u];

    const int  sx  = tid / 5, fx = tid - 5 * sx;
    const bool isx = tid < BS * F;

    // ---- init: zero all; x(0) into parity 0 ----
    // X2 pairing matches AE2: k0-4 carries x_hi (x Wlo'), k5-9 carries x_lo' (x Whi)
    for (int i = tid; i < TOTW; i += TPB) smw[i] = 0;
    __syncthreads();
    if (isx && n0 + sx < N) {
        float xv = feature[(size_t)(n0 + sx) * T * F + fx];
        __half xh = __float2half_rn(xv);
        __half xl = __float2half_rn((xv - __half2float(xh)) * 2048.f);
        hp[hw_idx(X1_W, fx, sx)]     = xh;
        hp[hw_idx(X2_W, fx, sx)]     = xh;   // Wlo' * x_hi
        hp[hw_idx(X2_W, 5 + fx, sx)] = xl;   // Whi  * x_lo'
    }
    __syncthreads();

    float c_reg[8];   // cell state for (nt, j): sample 8nt + 2tq + j
#pragma unroll
    for (int i = 0; i < 8; i++) c_reg[i] = 0.f;

    for (int t = 0; t < T; t++) {
        const int p = t & 1, pn = p ^ 1;
        const int pw = p * PW, pnw = pn * PW;

        float xv = 0.f;
        const bool xok = isx && (t + 1 < T) && (n0 + sx < N);
        if (xok) xv = feature[(size_t)(n0 + sx) * T * F + (size_t)(t + 1) * F + fx];

        float C1[2][4][4], C2[2][4][4];
#pragma unroll
        for (int mt = 0; mt < 2; mt++)
#pragma unroll
            for (int nt = 0; nt < 4; nt++)
#pragma unroll
                for (int q = 0; q < 4; q++) { C1[mt][nt][q] = 0.f; C2[mt][nt][q] = 0.f; }

        const uint2* pBH = (const uint2*)(smw + pw + BH_W);
        const uint2* pBL = (const uint2*)(smw + pw + BL_W);
        const uint2* pX1 = (const uint2*)(smw + pw + X1_W);
        const uint2* pX2 = (const uint2*)(smw + pw + X2_W);

        // ---- mma group per nt-pair (software pipeline: issue pair 1, then
        //      epilogue pair 0 overlaps the tensor pipe draining pair 1) ----
#pragma unroll
        for (int ntb = 0; ntb < 2; ntb++) {
#pragma unroll
            for (int kc = 0; kc < 4; kc++) {
                uint2 bh[2], bl[2];
#pragma unroll
                for (int q = 0; q < 2; q++) bh[q] = pBH[(kc * 4 + 2 * ntb + q) * 33 + lane];
#pragma unroll
                for (int mt = 0; mt < 2; mt++)
#pragma unroll
                    for (int q = 0; q < 2; q++)
                        mma16(C1[mt][2 * ntb + q], aHi[mt][kc], (const uint32_t*)&bh[q]);
#pragma unroll
                for (int q = 0; q < 2; q++) bl[q] = pBL[(kc * 4 + 2 * ntb + q) * 33 + lane];
#pragma unroll
                for (int mt = 0; mt < 2; mt++)
#pragma unroll
                    for (int q = 0; q < 2; q++)
                        mma16(C2[mt][2 * ntb + q], aLo[mt][kc], (const uint32_t*)&bh[q]);
#pragma unroll
                for (int mt = 0; mt < 2; mt++)
#pragma unroll
                    for (int q = 0; q < 2; q++)
                        mma16(C2[mt][2 * ntb + q], aHi[mt][kc], (const uint32_t*)&bl[q]);
            }
            uint2 x1[2], x2[2];
#pragma unroll
            for (int q = 0; q < 2; q++) {
                x1[q] = pX1[(2 * ntb + q) * 33 + lane];
                x2[q] = pX2[(2 * ntb + q) * 33 + lane];
            }
#pragma unroll
            for (int mt = 0; mt < 2; mt++)
#pragma unroll
                for (int q = 0; q < 2; q++) {
                    mma16(C1[mt][2 * ntb + q], AE1[mt], (const uint32_t*)&x1[q]);
                    mma16(C2[mt][2 * ntb + q], AE2[mt], (const uint32_t*)&x2[q]);
                }

            // after issuing pair 1's mma, run pair 0's epilogue (overlap)
            if (ntb == 1) {
#pragma unroll
                for (int pr = 0; pr < 2; pr++) {
#pragma unroll
                    for (int q = 0; q < 2; q++) {
                        const int nt = 2 * pr + q;
#pragma unroll
                        for (int j = 0; j < 2; j++) {
                            float ig = sig_hw(bi[0] + fmaf(SLO, C2[0][nt][j],     C1[0][nt][j]));
                            float fg = sig_hw(bi[1] + fmaf(SLO, C2[0][nt][2 + j], C1[0][nt][2 + j]));
                            float gg = tanh_hw(bi[2] + fmaf(SLO, C2[1][nt][j],    C1[1][nt][j]));
                            float og = sig_hw(bi[3] + fmaf(SLO, C2[1][nt][2 + j], C1[1][nt][2 + j]));
                            float c  = fg * c_reg[nt * 2 + j] + ig * gg;
                            c_reg[nt * 2 + j] = c;
                            float hv = og * tanh_hw(c);
                            const int s = 8 * nt + 2 * tq + j;
                            if (t < T - 1) {
                                __half hh = __float2half_rn(hv);
                                hp[pnw * 2 + hw_idx(BH_W, u, s)] = hh;
                                hp[pnw * 2 + hw_idx(BL_W, u, s)] =
                                    __float2half_rn((hv - __half2float(hh)) * 2048.f);
                            } else {
                                ((float*)(smw + HFIN_W))[u * 33 + s] = hv;
                            }
                        }
                    }
                }
            }
        }

        if (xok) {
            __half xh = __float2half_rn(xv);
            __half xl = __float2half_rn((xv - __half2float(xh)) * 2048.f);
            hp[pnw * 2 + hw_idx(X1_W, fx, sx)]     = xh;
            hp[pnw * 2 + hw_idx(X2_W, fx, sx)]     = xh;   // Wlo' * x_hi
            hp[pnw * 2 + hw_idx(X2_W, 5 + fx, sx)] = xl;   // Whi  * x_lo'
        }
        __syncthreads();
    }

    // ---- head: pred = leaky_relu(h . Wd + bd, 0.2); warp w -> samples 4w..4w+3
    const float* hf = (const float*)(smw + HFIN_W);
#pragma unroll
    for (int sl = 0; sl < 4; sl++) {
        const int s = 4 * w + sl;
        float pv = hf[lane * 33 + s] * Wd[lane]
                 + hf[(lane + 32) * 33 + s] * Wd[lane + 32];
#pragma unroll
        for (int off = 16; off; off >>= 1) pv += __shfl_down_sync(0xffffffffu, pv, off);
        if (lane == 0 && n0 + s < N) {
            pv += bd[0];
            pv = pv > 0.f ? pv : 0.2f * pv;
            pred[n0 + s] = pv;
        }
    }
}

// Pairwise rank loss partials + masked MSE partials (deterministic, no atomics).
__global__ void pair_kernel(const float* __restrict__ pred, const float* __restrict__ ret,
                            const unsigned* __restrict__ mask, int N)
{
    __shared__ float p_sm[4096];
    __shared__ float t_sm[4096];
    __shared__ unsigned char m_sm[4096];
    __shared__ float red[256];
    const int tid = threadIdx.x;

    for (int n = tid; n < N; n += blockDim.x) {
        p_sm[n] = pred[n];
        t_sm[n] = ret[n];
        m_sm[n] = (mask[n] != 0u) ? 1 : 0;
    }
    __syncthreads();

    float rsum = 0.f;
    for (int i = blockIdx.x; i < N; i += gridDim.x) {
        if (!m_sm[i]) continue;
        float pi = p_sm[i], gi = t_sm[i];
        for (int j = tid; j < N; j += blockDim.x) {
            float v = -(p_sm[j] - pi) * (t_sm[j] - gi);
            v = fmaxf(v, 0.f);
            rsum += v * (float)m_sm[j];
        }
    }
    red[tid] = rsum;
    __syncthreads();
    for (int s = 128; s; s >>= 1) { if (tid < s) red[tid] += red[tid + s]; __syncthreads(); }
    if (tid == 0) g_rank_part[blockIdx.x] = red[0];

    if (blockIdx.x == 0) {
        float ssq = 0.f, sm = 0.f;
        for (int n = tid; n < N; n += blockDim.x) {
            float m = (float)m_sm[n];
            float d = p_sm[n] - t_sm[n];
            ssq += d * d * m;
            sm  += m;
        }
        __syncthreads();
        red[tid] = ssq; __syncthreads();
        for (int s = 128; s; s >>= 1) { if (tid < s) red[tid] += red[tid + s]; __syncthreads(); }
        if (tid == 0) g_reg_part[0] = red[0];
        __syncthreads();
        red[tid] = sm; __syncthreads();
        for (int s = 128; s; s >>= 1) { if (tid < s) red[tid] += red[tid + s]; __syncthreads(); }
        if (tid == 0) g_reg_part[1] = red[0];
    }
}

__global__ void finalize_kernel(float* __restrict__ out, int N)
{
    if (threadIdx.x == 0 && blockIdx.x == 0) {
        float srank = 0.f;
        for (int b = 0; b < RB; b++) srank += g_rank_part[b];
        float reg  = g_reg_part[0] / (g_reg_part[1] + 1e-8f);
        float rank = srank / ((float)N * (float)N);
        out[N]     = reg + rank;
        out[N + 1] = reg;
        out[N + 2] = rank;
    }
}

extern "C" void kernel_launch(void* const* d_in, const int* in_sizes, int n_in,
                              void* d_out, int out_size)
{
    const float*    feature = (const float*)d_in[0];
    const float*    ret     = (const float*)d_in[1];
    const unsigned* mask    = (const unsigned*)d_in[2];
    const float*    Wih     = (const float*)d_in[3];
    const float*    Whh     = (const float*)d_in[4];
    const float*    bih     = (const float*)d_in[5];
    const float*    bhh     = (const float*)d_in[6];
    const float*    Wd      = (const float*)d_in[7];
    const float*    bd      = (const float*)d_in[8];
    float* out = (float*)d_out;

    const int N = in_sizes[1];                 // 4096
    const int T = in_sizes[0] / (N * F);       // 512

    const int grid = (N + BS - 1) / BS;        // 128
    lstm_kernel<<<grid, TPB>>>(feature, Wih, Whh, bih, bhh, Wd, bd, out, N, T);
    pair_kernel<<<RB, 256>>>(out, ret, mask, N);
    finalize_kernel<<<1, 32>>>(out, N);
}